// round 16
// baseline (speedup 1.0000x reference)
#include <cuda_runtime.h>
#include <cuda_fp16.h>
#include <math.h>
#include <stdint.h>

#define B_  32
#define N_  512
#define F_  512
#define H_  8
#define NB_ 128
#define G_  2048
#define NP1 513

// ---------------- scratch ------------------------------------------------------
__device__ __align__(16) __half g_uh[(size_t)B_ * N_ * 512];      // u (gated path)
__device__ __align__(16) __half g_attnh[(size_t)B_ * N_ * 512];
__device__ __align__(16) __half2 g_combo[(size_t)B_ * N_ * N_];   // (rel, mult) per (b,n,m)
__device__ int   g_ts32[B_ * NP1];
__device__ int   g_tflag[64];
__device__ __align__(16) __half g_Ah[(size_t)B_ * N_ * F_];
__device__ __align__(16) __half g_Wh[(size_t)G_ * F_];            // [n][k]
__device__ __align__(16) __half g_O2h[(size_t)B_ * N_ * 512];
__device__ __align__(16) __half g_W2h[(size_t)512 * 512];         // [n][k]
// head-major qkv, layout [b*H+h][n][64]
__device__ __align__(16) __half g_Qh[(size_t)B_ * H_ * N_ * 64];
__device__ __align__(16) __half g_Kh[(size_t)B_ * H_ * N_ * 64];
__device__ __align__(16) __half g_Vh[(size_t)B_ * H_ * N_ * 64];

// ---------------- helpers ------------------------------------------------------
__device__ __forceinline__ uint32_t smem_u32(const void* p) {
    uint32_t a;
    asm("{ .reg .u64 t; cvta.to.shared.u64 t, %1; cvt.u32.u64 %0, t; }" : "=r"(a) : "l"(p));
    return a;
}
__device__ __forceinline__ void cpa16(uint32_t dst, const void* src) {
    asm volatile("cp.async.cg.shared.global [%0], [%1], 16;" :: "r"(dst), "l"(src));
}
__device__ __forceinline__ void cpa_commit() { asm volatile("cp.async.commit_group;" ::: "memory"); }
__device__ __forceinline__ void cpa_wait1()  { asm volatile("cp.async.wait_group 1;" ::: "memory"); }
__device__ __forceinline__ void cpa_wait0()  { asm volatile("cp.async.wait_group 0;" ::: "memory"); }
__device__ __forceinline__ void ldsm_x4(uint32_t* r, uint32_t a) {
    asm volatile("ldmatrix.sync.aligned.m8n8.x4.shared.b16 {%0,%1,%2,%3}, [%4];"
        : "=r"(r[0]), "=r"(r[1]), "=r"(r[2]), "=r"(r[3]) : "r"(a));
}
__device__ __forceinline__ void ldsm_x4_t(uint32_t* r, uint32_t a) {
    asm volatile("ldmatrix.sync.aligned.m8n8.x4.trans.shared.b16 {%0,%1,%2,%3}, [%4];"
        : "=r"(r[0]), "=r"(r[1]), "=r"(r[2]), "=r"(r[3]) : "r"(a));
}
__device__ __forceinline__ void mma_f16(float* d, const uint32_t* a, const uint32_t* b) {
    asm volatile("mma.sync.aligned.m16n8k16.row.col.f32.f16.f16.f32 "
        "{%0,%1,%2,%3}, {%4,%5,%6,%7}, {%8,%9}, {%0,%1,%2,%3};"
        : "+f"(d[0]), "+f"(d[1]), "+f"(d[2]), "+f"(d[3])
        : "r"(a[0]), "r"(a[1]), "r"(a[2]), "r"(a[3]), "r"(b[0]), "r"(b[1]));
}
// silu via tanh.approx: sigmoid(x) = 0.5*tanh(x/2)+0.5
__device__ __forceinline__ float fast_silu(float x) {
    float t;
    asm("tanh.approx.f32 %0, %1;" : "=f"(t) : "f"(x * 0.5f));
    return x * fmaf(t, 0.5f, 0.5f);
}

// ---------------- timestamp canonicalization ----------------------------------
__global__ void ts_fix_kernel(const int* __restrict__ tsraw)
{
    __shared__ int is64;
    if (threadIdx.x == 0) {
        int z = 0;
        #pragma unroll
        for (int i = 1; i < 16; i += 2) z |= tsraw[i];
        is64 = (z == 0) ? 1 : 0;
    }
    __syncthreads();
    int i = blockIdx.x * blockDim.x + threadIdx.x;
    if (i < B_ * NP1) g_ts32[i] = is64 ? tsraw[2 * i] : tsraw[i];
}

// ---------------- per-tile mask flags ------------------------------------------
__global__ void tileflag_kernel(const float* __restrict__ amask)
{
    int t = blockIdx.x;
    int ti = t >> 3, tj = t & 7;
    int any = 0;
    for (int k = threadIdx.x; k < 1024; k += 256) {
        int r = k >> 4, c = (k & 15) * 4;
        float4 v = *(const float4*)(amask + (size_t)(ti * 64 + r) * N_ + tj * 64 + c);
        any |= (v.x != 0.f) | (v.y != 0.f) | (v.z != 0.f) | (v.w != 0.f);
    }
    any = __syncthreads_or(any);
    if (threadIdx.x == 0) g_tflag[t] = any;
}

// ---------------- fused rel+mult table (shared across heads) -------------------
__global__ void relprep_kernel(const float* __restrict__ tw,
                               const float* __restrict__ pw,
                               const float* __restrict__ amask,
                               const float* __restrict__ tl)
{
    int idx = blockIdx.x * 256 + threadIdx.x;          // quad index
    int b = idx >> 16;                                 // N*N/4 = 2^16 quads per batch
    int q = idx & 0xFFFF;
    int n = q >> 7;
    int mq = (q & 127) * 4;
    int tn = g_ts32[b * NP1 + n + 1];
    float tlnv = tl[b * N_ + n];
    float4 am = *(const float4*)(amask + (size_t)n * N_ + mq);
    const float* amp = &am.x;
    uint4 pk;
    uint32_t* pp = &pk.x;
    #pragma unroll
    for (int j = 0; j < 4; j++) {
        int m = mq + j;
        int dt = tn - g_ts32[b * NP1 + m];
        float ad = fmaxf(fabsf((float)dt), 1.0f);
        int bk = min(max((int)(__logf(ad) * (1.0f / 0.301f)), 0), NB_);
        float rel = tw[bk] + pw[N_ - 1 + m - n];
        float mult = amp[j] * tl[b * N_ + m] * tlnv;
        __half2 h = __floats2half2_rn(rel, mult);
        pp[j] = *(uint32_t*)&h;
    }
    *(uint4*)(g_combo + ((size_t)(b * N_ + n)) * N_ + mq) = pk;
}

// ---------------- W transpose + fp16 -------------------------------------------
__global__ void wprep_kernel(const float* __restrict__ W,
                             __half* __restrict__ hp, int ncols)
{
    __shared__ float t[32][33];
    int n0 = blockIdx.x * 32, k0 = blockIdx.y * 32;
    int tx = threadIdx.x, ty = threadIdx.y;   // 32 x 8
    #pragma unroll
    for (int j = 0; j < 4; j++)
        t[ty + j * 8][tx] = W[(size_t)(k0 + ty + j * 8) * ncols + n0 + tx];
    __syncthreads();
    #pragma unroll
    for (int j = 0; j < 4; j++) {
        int row = ty + j * 8;
        hp[(size_t)(n0 + row) * F_ + k0 + tx] = __float2half_rn(t[tx][row]);
    }
}

// ---------------- ln1: LayerNorm -> fp16 ---------------------------------------
__global__ void ln1_kernel(const float* __restrict__ x,
                           const float* __restrict__ tl)
{
    int row = blockIdx.x;
    int tid = threadIdx.x;
    const float* xr = x + (size_t)row * F_;
    float v0 = xr[tid], v1 = xr[tid + 256];
    float s = v0 + v1, sq = v0 * v0 + v1 * v1;
    #pragma unroll
    for (int o = 16; o; o >>= 1) {
        s  += __shfl_down_sync(0xffffffffu, s,  o);
        sq += __shfl_down_sync(0xffffffffu, sq, o);
    }
    __shared__ float red[16];
    __shared__ float mean_s, rstd_s;
    int w = tid >> 5, l = tid & 31;
    if (l == 0) { red[w] = s; red[w + 8] = sq; }
    __syncthreads();
    if (tid == 0) {
        float ts = 0.f, tq = 0.f;
        #pragma unroll
        for (int i = 0; i < 8; i++) { ts += red[i]; tq += red[i + 8]; }
        float m = ts * (1.0f / F_);
        float var = tq * (1.0f / F_) - m * m;
        mean_s = m;
        rstd_s = rsqrtf(var + 1e-6f);
    }
    __syncthreads();
    float t = tl[row];
    float m = mean_s, rs = rstd_s;
    size_t o0 = (size_t)row * F_ + tid;
    g_Ah[o0]       = __float2half_rn((v0 - m) * rs * t);
    g_Ah[o0 + 256] = __float2half_rn((v1 - m) * rs * t);
}

// ---------------- ln2: o_input = u*LN(attn)*tl -> fp16 -------------------------
__global__ void ln2_kernel(const float* __restrict__ tl)
{
    int row = blockIdx.x;
    int tid = threadIdx.x;
    const __half* ar = g_attnh + (size_t)row * 512;
    float v0 = __half2float(ar[tid]);
    float v1 = __half2float(ar[tid + 256]);
    float s = v0 + v1, sq = v0 * v0 + v1 * v1;
    #pragma unroll
    for (int o = 16; o; o >>= 1) {
        s  += __shfl_down_sync(0xffffffffu, s,  o);
        sq += __shfl_down_sync(0xffffffffu, sq, o);
    }
    __shared__ float red[16];
    __shared__ float mean_s, rstd_s;
    int w = tid >> 5, l = tid & 31;
    if (l == 0) { red[w] = s; red[w + 8] = sq; }
    __syncthreads();
    if (tid == 0) {
        float ts = 0.f, tq = 0.f;
        #pragma unroll
        for (int i = 0; i < 8; i++) { ts += red[i]; tq += red[i + 8]; }
        float m = ts * (1.0f / 512.0f);
        float var = tq * (1.0f / 512.0f) - m * m;
        mean_s = m;
        rstd_s = rsqrtf(var + 1e-6f);
    }
    __syncthreads();
    float t = tl[row];
    float m = mean_s, rs = rstd_s;
    float u0 = __half2float(g_uh[(size_t)row * 512 + tid]);
    float u1 = __half2float(g_uh[(size_t)row * 512 + tid + 256]);
    size_t off = (size_t)row * 512 + tid;
    g_O2h[off]       = __float2half_rn(u0 * (v0 - m) * rs * t);
    g_O2h[off + 256] = __float2half_rn(u1 * (v1 - m) * rs * t);
}

// ---------------- GEMM: 256x128 tile, mma.sync fp16, 3-stage, 1 sync/iter ------
// per stage: A 256x32 half = 20480 B at +0, B 128x32 half = 10240 B at +20480
#define GST 30720
#define GEMM_SMEM (3 * GST)

template <int MODE>
__global__ void __launch_bounds__(256)
gemm_mma(const __half* __restrict__ Ah, const __half* __restrict__ Bh,
         const float* __restrict__ tl, const float* __restrict__ bias,
         const float* __restrict__ xres, float* __restrict__ Cout)
{
    constexpr int LDS = 40;
    extern __shared__ __align__(16) char dsm[];
    const uint32_t sb = smem_u32(dsm);

    const int tid = threadIdx.x, lane = tid & 31, wid = tid >> 5;
    const int wr = wid & 3, wc = wid >> 2;
    const int m0 = blockIdx.y * 256, n0 = blockIdx.x * 128;

    float d[4][8][4] = {};

    auto load_stage = [&](int kc, int st) {
        const int k0 = kc * 32;
        const uint32_t base = sb + st * GST;
        #pragma unroll
        for (int it = 0; it < 4; it++) {      // A: 256 rows
            int idx = tid + it * 256;
            int r = idx >> 2, c = (idx & 3) * 8;
            cpa16(base + (uint32_t)(r * LDS + c) * 2,
                  Ah + (size_t)(m0 + r) * F_ + k0 + c);
        }
        #pragma unroll
        for (int it = 0; it < 2; it++) {      // B: 128 rows
            int idx = tid + it * 256;
            int r = idx >> 2, c = (idx & 3) * 8;
            cpa16(base + 20480 + (uint32_t)(r * LDS + c) * 2,
                  Bh + (size_t)(n0 + r) * F_ + k0 + c);
        }
        cpa_commit();
    };

    load_stage(0, 0);
    load_stage(1, 1);

    for (int kc = 0; kc < 16; kc++) {
        if (kc + 1 < 16) cpa_wait1(); else cpa_wait0();
        __syncthreads();                 // also releases buffer (kc-1)%3
        if (kc + 2 < 16) load_stage(kc + 2, (kc + 2) % 3);

        const uint32_t base = sb + (kc % 3) * GST;
        #pragma unroll
        for (int ks = 0; ks < 2; ks++) {
            uint32_t a[4][4], bb[4][4];
            const int g2 = lane >> 3;     // 0..3
            #pragma unroll
            for (int mi = 0; mi < 4; mi++) {
                int row = wr * 64 + mi * 16 + (lane & 15);
                uint32_t off = (uint32_t)(row * LDS + ks * 16 + (lane >> 4) * 8) * 2;
                ldsm_x4(a[mi], base + off);
            }
            #pragma unroll
            for (int nj = 0; nj < 4; nj++) {
                int row = wc * 64 + nj * 16 + (g2 >> 1) * 8 + (lane & 7);
                int col = ks * 16 + (g2 & 1) * 8;
                ldsm_x4(bb[nj], base + 20480 + (uint32_t)(row * LDS + col) * 2);
            }
            #pragma unroll
            for (int mi = 0; mi < 4; mi++)
                #pragma unroll
                for (int nj = 0; nj < 4; nj++) {
                    mma_f16(d[mi][2 * nj + 0], a[mi], &bb[nj][0]);
                    mma_f16(d[mi][2 * nj + 1], a[mi], &bb[nj][2]);
                }
        }
    }

    #pragma unroll
    for (int mi = 0; mi < 4; mi++) {
        int rbase = m0 + wr * 64 + mi * 16 + (lane >> 2);
        #pragma unroll
        for (int half = 0; half < 2; half++) {
            int row = rbase + half * 8;
            float tlv = (MODE == 1) ? tl[row] : 0.0f;
            #pragma unroll
            for (int ni = 0; ni < 8; ni++) {
                int col = n0 + wc * 64 + ni * 8 + (lane & 3) * 2;
                float v0 = d[mi][ni][half * 2 + 0];
                float v1 = d[mi][ni][half * 2 + 1];
                if (MODE == 1) {
                    v0 = fast_silu(v0) * tlv;
                    v1 = fast_silu(v1) * tlv;
                    __half2 hp = __floats2half2_rn(v0, v1);
                    if (col < 512) {
                        *(__half2*)(g_uh + (size_t)row * 512 + col) = hp;
                    } else {
                        int hh = (col >> 6) & 7;
                        int dd = col & 63;
                        size_t off = (((size_t)(row >> 9) * H_ + hh) * N_ + (row & 511)) * 64 + dd;
                        if (col < 1024)      *(__half2*)(g_Vh + off) = hp;
                        else if (col < 1536) *(__half2*)(g_Qh + off) = hp;
                        else                 *(__half2*)(g_Kh + off) = hp;
                    }
                } else {
                    v0 += bias[col]     + xres[(size_t)row * 512 + col];
                    v1 += bias[col + 1] + xres[(size_t)row * 512 + col + 1];
                    *(float2*)(Cout + (size_t)row * 512 + col) = make_float2(v0, v1);
                }
            }
        }
    }
}

// ---------------- tensor-core attention: 128 q-rows, 3-stage KV, 1 sync/iter ---
#define DS    72
#define SQ    0
#define SKV0  18432         // per stage: K +0, V +9216; stage size 18432
#define KVST  18432
#define SP    (SKV0 + 3 * KVST)          // 73728
#define ATT_SMEM (SP + 18432)            // 92160

__global__ void __launch_bounds__(256)
attn_tc()
{
    extern __shared__ __align__(16) char sm[];
    const uint32_t sb = smem_u32(sm);
    const int tid = threadIdx.x, lane = tid & 31, w = tid >> 5;
    const int n0 = blockIdx.x * 128, h = blockIdx.y, b = blockIdx.z;
    const int bh = b * H_ + h;

    // Q -> smem (128 rows)
    #pragma unroll
    for (int it = 0; it < 4; it++) {
        int idx = tid + it * 256;
        int r = idx >> 3, c = (idx & 7) * 8;
        *(float4*)(sm + SQ + (r * DS + c) * 2) =
            *(const float4*)(g_Qh + ((size_t)bh * N_ + n0 + r) * 64 + c);
    }

    int mlist[8];
    int nact = 0;
    const int tr = n0 >> 6;
    #pragma unroll
    for (int t = 0; t < 8; t++)
        if (g_tflag[tr * 8 + t] | g_tflag[(tr + 1) * 8 + t]) mlist[nact++] = t * 64;

    auto load_kv = [&](int m0, int st) {
        const uint32_t base = sb + SKV0 + st * KVST;
        #pragma unroll
        for (int it = 0; it < 2; it++) {
            int idx = tid + it * 256;
            int r = idx >> 3, c = (idx & 7) * 8;
            uint32_t doff = (uint32_t)(r * DS + c) * 2;
            size_t src = ((size_t)bh * N_ + m0 + r) * 64 + c;
            cpa16(base + doff,        g_Kh + src);
            cpa16(base + 9216 + doff, g_Vh + src);
        }
        cpa_commit();
    };

    if (nact > 0) load_kv(mlist[0], 0);
    if (nact > 1) load_kv(mlist[1], 1);

    __syncthreads();                       // Q visible to all warps

    // hoist Q fragments (reused across all tiles)
    uint32_t qf[4][4];
    {
        int arow = w * 16 + (lane & 15);
        #pragma unroll
        for (int ks = 0; ks < 4; ks++) {
            uint32_t aoff = (uint32_t)(arow * DS + ks * 16 + (lane >> 4) * 8) * 2;
            ldsm_x4(qf[ks], sb + SQ + aoff);
        }
    }

    float o[8][4] = {};

    for (int i = 0; i < nact; i++) {
        if (i + 1 < nact) cpa_wait1(); else cpa_wait0();
        __syncthreads();                   // releases KV buffer (i-1)%3
        if (i + 2 < nact) load_kv(mlist[i + 2], (i + 2) % 3);

        const int m0 = mlist[i];
        const uint32_t kb = sb + SKV0 + (i % 3) * KVST;
        const int g2 = lane >> 3;

        // S = Q K^T
        float s[8][4] = {};
        #pragma unroll
        for (int ks = 0; ks < 4; ks++) {
            #pragma unroll
            for (int t = 0; t < 4; t++) {
                uint32_t kk[4];
                int brow = t * 16 + (g2 >> 1) * 8 + (lane & 7);
                int bcol = ks * 16 + (g2 & 1) * 8;
                ldsm_x4(kk, kb + (uint32_t)(brow * DS + bcol) * 2);
                mma_f16(s[2 * t + 0], qf[ks], &kk[0]);
                mma_f16(s[2 * t + 1], qf[ks], &kk[2]);
            }
        }

        // epilogue: fused (rel, mult) table; P unscaled by 1/N (folded into O)
        #pragma unroll
        for (int half = 0; half < 2; half++) {
            int r = w * 16 + (lane >> 2) + half * 8;
            int n = n0 + r;
            const __half2* crow = g_combo + ((size_t)(b * N_ + n)) * N_;
            #pragma unroll
            for (int ni = 0; ni < 8; ni++) {
                int c = ni * 8 + (lane & 3) * 2;
                int m = m0 + c;
                uint2 pk = *(const uint2*)(crow + m);
                float2 f0 = __half22float2(*(__half2*)&pk.x);
                float2 f1 = __half22float2(*(__half2*)&pk.y);
                float x0 = fast_silu(s[ni][half * 2 + 0] + f0.x) * f0.y;
                float x1 = fast_silu(s[ni][half * 2 + 1] + f1.x) * f1.y;
                __half2 hp = __floats2half2_rn(x0, x1);
                *(uint32_t*)(sm + SP + (r * DS + c) * 2) = *(uint32_t*)&hp;
            }
        }
        __syncwarp();                      // P rows are warp-private

        // O += P V; V via ldmatrix.trans x4
        #pragma unroll
        for (int ks = 0; ks < 4; ks++) {
            uint32_t p[4];
            int arow = w * 16 + (lane & 15);
            uint32_t aoff = (uint32_t)(arow * DS + ks * 16 + (lane >> 4) * 8) * 2;
            ldsm_x4(p, sb + SP + aoff);
            #pragma unroll
            for (int t = 0; t < 4; t++) {
                uint32_t v[4];
                int vrow = ks * 16 + (lane & 15);
                int vcol = (2 * t + (lane >> 4)) * 8;
                ldsm_x4_t(v, kb + 9216 + (uint32_t)(vrow * DS + vcol) * 2);
                mma_f16(o[2 * t + 0], p, &v[0]);
                mma_f16(o[2 * t + 1], p, &v[2]);
            }
        }
    }

    #pragma unroll
    for (int half = 0; half < 2; half++) {
        int r = w * 16 + (lane >> 2) + half * 8;
        int n = n0 + r;
        #pragma unroll
        for (int ni = 0; ni < 8; ni++) {
            int c = ni * 8 + (lane & 3) * 2;
            __half2 hp = __floats2half2_rn(o[ni][half * 2] * (1.0f / N_),
                                           o[ni][half * 2 + 1] * (1.0f / N_));
            *(__half2*)(g_attnh + ((size_t)(b * N_ + n)) * 512 + h * 64 + c) = hp;
        }
    }
}

// ---------------- launch -------------------------------------------------------
extern "C" void kernel_launch(void* const* d_in, const int* in_sizes, int n_in,
                              void* d_out, int out_size)
{
    const float* x      = (const float*)d_in[0];
    const float* tlmask = (const float*)d_in[1];
    const float* amask  = (const float*)d_in[2];
    const float* uvqk   = (const float*)d_in[3];
    const float* out_w  = (const float*)d_in[4];
    const float* out_b  = (const float*)d_in[5];
    const float* tw     = (const float*)d_in[6];
    const float* pw     = (const float*)d_in[7];
    const int*   tsraw  = (const int*)d_in[8];
    float*       out    = (float*)d_out;

    const int rows = B_ * N_;   // 16384

    __half *wh, *w2h, *ah, *o2h;
    cudaGetSymbolAddress((void**)&wh,  g_Wh);
    cudaGetSymbolAddress((void**)&w2h, g_W2h);
    cudaGetSymbolAddress((void**)&ah,  g_Ah);
    cudaGetSymbolAddress((void**)&o2h, g_O2h);

    cudaFuncSetAttribute(gemm_mma<1>, cudaFuncAttributeMaxDynamicSharedMemorySize, GEMM_SMEM);
    cudaFuncSetAttribute(gemm_mma<2>, cudaFuncAttributeMaxDynamicSharedMemorySize, GEMM_SMEM);
    cudaFuncSetAttribute(attn_tc, cudaFuncAttributeMaxDynamicSharedMemorySize, ATT_SMEM);

    ts_fix_kernel<<<(B_ * NP1 + 255) / 256, 256>>>(tsraw);
    tileflag_kernel<<<64, 256>>>(amask);
    wprep_kernel<<<dim3(G_ / 32, F_ / 32), dim3(32, 8)>>>(uvqk, wh, G_);
    wprep_kernel<<<dim3(512 / 32, F_ / 32), dim3(32, 8)>>>(out_w, w2h, 512);
    ln1_kernel<<<rows, 256>>>(x, tlmask);

    dim3 g1(G_ / 128, rows / 256);        // (16, 64) = 1024 blocks
    gemm_mma<1><<<g1, 256, GEMM_SMEM>>>(ah, wh, tlmask, nullptr, nullptr, nullptr);

    relprep_kernel<<<B_ * N_ * N_ / 1024, 256>>>(tw, pw, amask, tlmask);

    dim3 ga(N_ / 128, H_, B_);
    attn_tc<<<ga, 256, ATT_SMEM>>>();

    ln2_kernel<<<rows, 256>>>(tlmask);

    dim3 g2(512 / 128, rows / 256);       // (4, 64) = 256 blocks
    gemm_mma<2><<<g2, 256, GEMM_SMEM>>>(o2h, w2h, nullptr, out_b, x, out);
}

// round 17
// speedup vs baseline: 1.1088x; 1.1088x over previous
#include <cuda_runtime.h>
#include <cuda_fp16.h>
#include <math.h>
#include <stdint.h>

#define B_  32
#define N_  512
#define F_  512
#define H_  8
#define NB_ 128
#define G_  2048
#define NP1 513

// ---------------- scratch ------------------------------------------------------
__device__ __align__(16) __half g_uh[(size_t)B_ * N_ * 512];      // u (gated path)
__device__ __align__(16) __half g_attnh[(size_t)B_ * N_ * 512];
__device__ __align__(16) __half2 g_combo[(size_t)B_ * N_ * N_];   // (rel, mult) per (b,n,m)
__device__ int   g_ts32[B_ * NP1];
__device__ int   g_tflag[64];
__device__ __align__(16) __half g_Ah[(size_t)B_ * N_ * F_];
__device__ __align__(16) __half g_Wh[(size_t)G_ * F_];            // [n][k]
__device__ __align__(16) __half g_O2h[(size_t)B_ * N_ * 512];
__device__ __align__(16) __half g_W2h[(size_t)512 * 512];         // [n][k]
// head-major qkv, layout [b*H+h][n][64]
__device__ __align__(16) __half g_Qh[(size_t)B_ * H_ * N_ * 64];
__device__ __align__(16) __half g_Kh[(size_t)B_ * H_ * N_ * 64];
__device__ __align__(16) __half g_Vh[(size_t)B_ * H_ * N_ * 64];

// ---------------- helpers ------------------------------------------------------
__device__ __forceinline__ uint32_t smem_u32(const void* p) {
    uint32_t a;
    asm("{ .reg .u64 t; cvta.to.shared.u64 t, %1; cvt.u32.u64 %0, t; }" : "=r"(a) : "l"(p));
    return a;
}
__device__ __forceinline__ void cpa16(uint32_t dst, const void* src) {
    asm volatile("cp.async.cg.shared.global [%0], [%1], 16;" :: "r"(dst), "l"(src));
}
__device__ __forceinline__ void cpa_commit() { asm volatile("cp.async.commit_group;" ::: "memory"); }
__device__ __forceinline__ void cpa_wait1()  { asm volatile("cp.async.wait_group 1;" ::: "memory"); }
__device__ __forceinline__ void cpa_wait0()  { asm volatile("cp.async.wait_group 0;" ::: "memory"); }
__device__ __forceinline__ void ldsm_x4(uint32_t* r, uint32_t a) {
    asm volatile("ldmatrix.sync.aligned.m8n8.x4.shared.b16 {%0,%1,%2,%3}, [%4];"
        : "=r"(r[0]), "=r"(r[1]), "=r"(r[2]), "=r"(r[3]) : "r"(a));
}
__device__ __forceinline__ void ldsm_x4_t(uint32_t* r, uint32_t a) {
    asm volatile("ldmatrix.sync.aligned.m8n8.x4.trans.shared.b16 {%0,%1,%2,%3}, [%4];"
        : "=r"(r[0]), "=r"(r[1]), "=r"(r[2]), "=r"(r[3]) : "r"(a));
}
__device__ __forceinline__ void mma_f16(float* d, const uint32_t* a, const uint32_t* b) {
    asm volatile("mma.sync.aligned.m16n8k16.row.col.f32.f16.f16.f32 "
        "{%0,%1,%2,%3}, {%4,%5,%6,%7}, {%8,%9}, {%0,%1,%2,%3};"
        : "+f"(d[0]), "+f"(d[1]), "+f"(d[2]), "+f"(d[3])
        : "r"(a[0]), "r"(a[1]), "r"(a[2]), "r"(a[3]), "r"(b[0]), "r"(b[1]));
}
// silu via tanh.approx: sigmoid(x) = 0.5*tanh(x/2)+0.5
__device__ __forceinline__ float fast_silu(float x) {
    float t;
    asm("tanh.approx.f32 %0, %1;" : "=f"(t) : "f"(x * 0.5f));
    return x * fmaf(t, 0.5f, 0.5f);
}

// ---------------- timestamp canonicalization ----------------------------------
__global__ void ts_fix_kernel(const int* __restrict__ tsraw)
{
    __shared__ int is64;
    if (threadIdx.x == 0) {
        int z = 0;
        #pragma unroll
        for (int i = 1; i < 16; i += 2) z |= tsraw[i];
        is64 = (z == 0) ? 1 : 0;
    }
    __syncthreads();
    int i = blockIdx.x * blockDim.x + threadIdx.x;
    if (i < B_ * NP1) g_ts32[i] = is64 ? tsraw[2 * i] : tsraw[i];
}

// ---------------- per-tile mask flags ------------------------------------------
__global__ void tileflag_kernel(const float* __restrict__ amask)
{
    int t = blockIdx.x;
    int ti = t >> 3, tj = t & 7;
    int any = 0;
    for (int k = threadIdx.x; k < 1024; k += 256) {
        int r = k >> 4, c = (k & 15) * 4;
        float4 v = *(const float4*)(amask + (size_t)(ti * 64 + r) * N_ + tj * 64 + c);
        any |= (v.x != 0.f) | (v.y != 0.f) | (v.z != 0.f) | (v.w != 0.f);
    }
    any = __syncthreads_or(any);
    if (threadIdx.x == 0) g_tflag[t] = any;
}

// ---------------- fused rel+mult table (shared across heads, tile-skipped) -----
// Dead tiles (g_tflag==0) are never read by attn_tc, so skip computing them.
__global__ void relprep_kernel(const float* __restrict__ tw,
                               const float* __restrict__ pw,
                               const float* __restrict__ amask,
                               const float* __restrict__ tl)
{
    int idx = blockIdx.x * 256 + threadIdx.x;          // quad index
    int b = idx >> 16;                                 // N*N/4 = 2^16 quads per batch
    int q = idx & 0xFFFF;
    int n = q >> 7;
    int mq = (q & 127) * 4;
    if (!g_tflag[(n >> 6) * 8 + (mq >> 6)]) return;    // causal tile skip
    int tn = g_ts32[b * NP1 + n + 1];
    float tlnv = tl[b * N_ + n];
    float4 am = *(const float4*)(amask + (size_t)n * N_ + mq);
    const float* amp = &am.x;
    uint4 pk;
    uint32_t* pp = &pk.x;
    #pragma unroll
    for (int j = 0; j < 4; j++) {
        int m = mq + j;
        int dt = tn - g_ts32[b * NP1 + m];
        float ad = fmaxf(fabsf((float)dt), 1.0f);
        int bk = min(max((int)(__logf(ad) * (1.0f / 0.301f)), 0), NB_);
        float rel = tw[bk] + pw[N_ - 1 + m - n];
        float mult = amp[j] * tl[b * N_ + m] * tlnv;
        __half2 h = __floats2half2_rn(rel, mult);
        pp[j] = *(uint32_t*)&h;
    }
    *(uint4*)(g_combo + ((size_t)(b * N_ + n)) * N_ + mq) = pk;
}

// ---------------- W transpose + fp16 -------------------------------------------
__global__ void wprep_kernel(const float* __restrict__ W,
                             __half* __restrict__ hp, int ncols)
{
    __shared__ float t[32][33];
    int n0 = blockIdx.x * 32, k0 = blockIdx.y * 32;
    int tx = threadIdx.x, ty = threadIdx.y;   // 32 x 8
    #pragma unroll
    for (int j = 0; j < 4; j++)
        t[ty + j * 8][tx] = W[(size_t)(k0 + ty + j * 8) * ncols + n0 + tx];
    __syncthreads();
    #pragma unroll
    for (int j = 0; j < 4; j++) {
        int row = ty + j * 8;
        hp[(size_t)(n0 + row) * F_ + k0 + tx] = __float2half_rn(t[tx][row]);
    }
}

// ---------------- ln1: LayerNorm -> fp16 ---------------------------------------
__global__ void ln1_kernel(const float* __restrict__ x,
                           const float* __restrict__ tl)
{
    int row = blockIdx.x;
    int tid = threadIdx.x;
    const float* xr = x + (size_t)row * F_;
    float v0 = xr[tid], v1 = xr[tid + 256];
    float s = v0 + v1, sq = v0 * v0 + v1 * v1;
    #pragma unroll
    for (int o = 16; o; o >>= 1) {
        s  += __shfl_down_sync(0xffffffffu, s,  o);
        sq += __shfl_down_sync(0xffffffffu, sq, o);
    }
    __shared__ float red[16];
    __shared__ float mean_s, rstd_s;
    int w = tid >> 5, l = tid & 31;
    if (l == 0) { red[w] = s; red[w + 8] = sq; }
    __syncthreads();
    if (tid == 0) {
        float ts = 0.f, tq = 0.f;
        #pragma unroll
        for (int i = 0; i < 8; i++) { ts += red[i]; tq += red[i + 8]; }
        float m = ts * (1.0f / F_);
        float var = tq * (1.0f / F_) - m * m;
        mean_s = m;
        rstd_s = rsqrtf(var + 1e-6f);
    }
    __syncthreads();
    float t = tl[row];
    float m = mean_s, rs = rstd_s;
    size_t o0 = (size_t)row * F_ + tid;
    g_Ah[o0]       = __float2half_rn((v0 - m) * rs * t);
    g_Ah[o0 + 256] = __float2half_rn((v1 - m) * rs * t);
}

// ---------------- ln2: o_input = u*LN(attn)*tl -> fp16 -------------------------
__global__ void ln2_kernel(const float* __restrict__ tl)
{
    int row = blockIdx.x;
    int tid = threadIdx.x;
    const __half* ar = g_attnh + (size_t)row * 512;
    float v0 = __half2float(ar[tid]);
    float v1 = __half2float(ar[tid + 256]);
    float s = v0 + v1, sq = v0 * v0 + v1 * v1;
    #pragma unroll
    for (int o = 16; o; o >>= 1) {
        s  += __shfl_down_sync(0xffffffffu, s,  o);
        sq += __shfl_down_sync(0xffffffffu, sq, o);
    }
    __shared__ float red[16];
    __shared__ float mean_s, rstd_s;
    int w = tid >> 5, l = tid & 31;
    if (l == 0) { red[w] = s; red[w + 8] = sq; }
    __syncthreads();
    if (tid == 0) {
        float ts = 0.f, tq = 0.f;
        #pragma unroll
        for (int i = 0; i < 8; i++) { ts += red[i]; tq += red[i + 8]; }
        float m = ts * (1.0f / 512.0f);
        float var = tq * (1.0f / 512.0f) - m * m;
        mean_s = m;
        rstd_s = rsqrtf(var + 1e-6f);
    }
    __syncthreads();
    float t = tl[row];
    float m = mean_s, rs = rstd_s;
    float u0 = __half2float(g_uh[(size_t)row * 512 + tid]);
    float u1 = __half2float(g_uh[(size_t)row * 512 + tid + 256]);
    size_t off = (size_t)row * 512 + tid;
    g_O2h[off]       = __float2half_rn(u0 * (v0 - m) * rs * t);
    g_O2h[off + 256] = __float2half_rn(u1 * (v1 - m) * rs * t);
}

// ---------------- GEMM via mma.sync fp16, cp.async 3-stage, 1 sync/iter --------
// per stage 20480 B: A +0, B +10240
#define GST 20480
#define GEMM_SMEM (3 * GST)

template <int MODE>
__global__ void __launch_bounds__(256)
gemm_mma(const __half* __restrict__ Ah, const __half* __restrict__ Bh,
         const float* __restrict__ tl, const float* __restrict__ bias,
         const float* __restrict__ xres, float* __restrict__ Cout)
{
    constexpr int LDS = 40;
    extern __shared__ __align__(16) char dsm[];
    const uint32_t sb = smem_u32(dsm);

    const int tid = threadIdx.x, lane = tid & 31, wid = tid >> 5;
    const int wr = wid & 3, wc = wid >> 2;
    const int m0 = blockIdx.y * 128, n0 = blockIdx.x * 128;

    float d[2][8][4] = {};

    auto load_stage = [&](int kc, int st) {
        const int k0 = kc * 32;
        const uint32_t base = sb + st * GST;
        #pragma unroll
        for (int it = 0; it < 2; it++) {
            int idx = tid + it * 256;
            int r = idx >> 2, c = (idx & 3) * 8;
            uint32_t doff = (uint32_t)(r * LDS + c) * 2;
            cpa16(base + doff,         Ah + (size_t)(m0 + r) * F_ + k0 + c);
            cpa16(base + 10240 + doff, Bh + (size_t)(n0 + r) * F_ + k0 + c);
        }
        cpa_commit();
    };

    load_stage(0, 0);
    load_stage(1, 1);

    for (int kc = 0; kc < 16; kc++) {
        if (kc + 1 < 16) cpa_wait1(); else cpa_wait0();
        __syncthreads();                 // also releases buffer (kc-1)%3
        if (kc + 2 < 16) load_stage(kc + 2, (kc + 2) % 3);

        const uint32_t base = sb + (kc % 3) * GST;
        #pragma unroll
        for (int ks = 0; ks < 2; ks++) {
            uint32_t a[2][4], bb[4][4];
            const int g2 = lane >> 3;     // 0..3
            #pragma unroll
            for (int mi = 0; mi < 2; mi++) {
                int row = wr * 32 + mi * 16 + (lane & 15);
                uint32_t off = (uint32_t)(row * LDS + ks * 16 + (lane >> 4) * 8) * 2;
                ldsm_x4(a[mi], base + off);
            }
            #pragma unroll
            for (int nj = 0; nj < 4; nj++) {
                int row = wc * 64 + nj * 16 + (g2 >> 1) * 8 + (lane & 7);
                int col = ks * 16 + (g2 & 1) * 8;
                ldsm_x4(bb[nj], base + 10240 + (uint32_t)(row * LDS + col) * 2);
            }
            #pragma unroll
            for (int mi = 0; mi < 2; mi++)
                #pragma unroll
                for (int nj = 0; nj < 4; nj++) {
                    mma_f16(d[mi][2 * nj + 0], a[mi], &bb[nj][0]);
                    mma_f16(d[mi][2 * nj + 1], a[mi], &bb[nj][2]);
                }
        }
    }

    #pragma unroll
    for (int mi = 0; mi < 2; mi++) {
        int rbase = m0 + wr * 32 + mi * 16 + (lane >> 2);
        #pragma unroll
        for (int half = 0; half < 2; half++) {
            int row = rbase + half * 8;
            float tlv = (MODE == 1) ? tl[row] : 0.0f;
            #pragma unroll
            for (int ni = 0; ni < 8; ni++) {
                int col = n0 + wc * 64 + ni * 8 + (lane & 3) * 2;
                float v0 = d[mi][ni][half * 2 + 0];
                float v1 = d[mi][ni][half * 2 + 1];
                if (MODE == 1) {
                    v0 = fast_silu(v0) * tlv;
                    v1 = fast_silu(v1) * tlv;
                    __half2 hp = __floats2half2_rn(v0, v1);
                    if (col < 512) {
                        *(__half2*)(g_uh + (size_t)row * 512 + col) = hp;
                    } else {
                        int hh = (col >> 6) & 7;
                        int dd = col & 63;
                        size_t off = (((size_t)(row >> 9) * H_ + hh) * N_ + (row & 511)) * 64 + dd;
                        if (col < 1024)      *(__half2*)(g_Vh + off) = hp;
                        else if (col < 1536) *(__half2*)(g_Qh + off) = hp;
                        else                 *(__half2*)(g_Kh + off) = hp;
                    }
                } else {
                    v0 += bias[col]     + xres[(size_t)row * 512 + col];
                    v1 += bias[col + 1] + xres[(size_t)row * 512 + col + 1];
                    *(float2*)(Cout + (size_t)row * 512 + col) = make_float2(v0, v1);
                }
            }
        }
    }
}

// ---------------- tensor-core attention: 128 q-rows, 3-stage KV, 1 sync/iter ---
#define DS    72
#define SQ    0
#define SKV0  18432         // per stage: K +0, V +9216; stage size 18432
#define KVST  18432
#define SP    (SKV0 + 3 * KVST)          // 73728
#define ATT_SMEM (SP + 18432)            // 92160

__global__ void __launch_bounds__(256)
attn_tc()
{
    extern __shared__ __align__(16) char sm[];
    const uint32_t sb = smem_u32(sm);
    const int tid = threadIdx.x, lane = tid & 31, w = tid >> 5;
    const int n0 = blockIdx.x * 128, h = blockIdx.y, b = blockIdx.z;
    const int bh = b * H_ + h;

    // Q -> smem (128 rows)
    #pragma unroll
    for (int it = 0; it < 4; it++) {
        int idx = tid + it * 256;
        int r = idx >> 3, c = (idx & 7) * 8;
        *(float4*)(sm + SQ + (r * DS + c) * 2) =
            *(const float4*)(g_Qh + ((size_t)bh * N_ + n0 + r) * 64 + c);
    }

    int mlist[8];
    int nact = 0;
    const int tr = n0 >> 6;
    #pragma unroll
    for (int t = 0; t < 8; t++)
        if (g_tflag[tr * 8 + t] | g_tflag[(tr + 1) * 8 + t]) mlist[nact++] = t * 64;

    auto load_kv = [&](int m0, int st) {
        const uint32_t base = sb + SKV0 + st * KVST;
        #pragma unroll
        for (int it = 0; it < 2; it++) {
            int idx = tid + it * 256;
            int r = idx >> 3, c = (idx & 7) * 8;
            uint32_t doff = (uint32_t)(r * DS + c) * 2;
            size_t src = ((size_t)bh * N_ + m0 + r) * 64 + c;
            cpa16(base + doff,        g_Kh + src);
            cpa16(base + 9216 + doff, g_Vh + src);
        }
        cpa_commit();
    };

    if (nact > 0) load_kv(mlist[0], 0);
    if (nact > 1) load_kv(mlist[1], 1);

    __syncthreads();                       // Q visible to all warps

    // hoist Q fragments (reused across all tiles)
    uint32_t qf[4][4];
    {
        int arow = w * 16 + (lane & 15);
        #pragma unroll
        for (int ks = 0; ks < 4; ks++) {
            uint32_t aoff = (uint32_t)(arow * DS + ks * 16 + (lane >> 4) * 8) * 2;
            ldsm_x4(qf[ks], sb + SQ + aoff);
        }
    }

    float o[8][4] = {};

    for (int i = 0; i < nact; i++) {
        if (i + 1 < nact) cpa_wait1(); else cpa_wait0();
        __syncthreads();                   // releases KV buffer (i-1)%3
        if (i + 2 < nact) load_kv(mlist[i + 2], (i + 2) % 3);

        const int m0 = mlist[i];
        const uint32_t kb = sb + SKV0 + (i % 3) * KVST;
        const int g2 = lane >> 3;

        // S = Q K^T
        float s[8][4] = {};
        #pragma unroll
        for (int ks = 0; ks < 4; ks++) {
            #pragma unroll
            for (int t = 0; t < 4; t++) {
                uint32_t kk[4];
                int brow = t * 16 + (g2 >> 1) * 8 + (lane & 7);
                int bcol = ks * 16 + (g2 & 1) * 8;
                ldsm_x4(kk, kb + (uint32_t)(brow * DS + bcol) * 2);
                mma_f16(s[2 * t + 0], qf[ks], &kk[0]);
                mma_f16(s[2 * t + 1], qf[ks], &kk[2]);
            }
        }

        // epilogue: fused (rel, mult) table; P unscaled by 1/N (folded into O)
        #pragma unroll
        for (int half = 0; half < 2; half++) {
            int r = w * 16 + (lane >> 2) + half * 8;
            int n = n0 + r;
            const __half2* crow = g_combo + ((size_t)(b * N_ + n)) * N_;
            #pragma unroll
            for (int ni = 0; ni < 8; ni++) {
                int c = ni * 8 + (lane & 3) * 2;
                int m = m0 + c;
                uint2 pk = *(const uint2*)(crow + m);
                float2 f0 = __half22float2(*(__half2*)&pk.x);
                float2 f1 = __half22float2(*(__half2*)&pk.y);
                float x0 = fast_silu(s[ni][half * 2 + 0] + f0.x) * f0.y;
                float x1 = fast_silu(s[ni][half * 2 + 1] + f1.x) * f1.y;
                __half2 hp = __floats2half2_rn(x0, x1);
                *(uint32_t*)(sm + SP + (r * DS + c) * 2) = *(uint32_t*)&hp;
            }
        }
        __syncwarp();                      // P rows are warp-private

        // O += P V; V via ldmatrix.trans x4
        #pragma unroll
        for (int ks = 0; ks < 4; ks++) {
            uint32_t p[4];
            int arow = w * 16 + (lane & 15);
            uint32_t aoff = (uint32_t)(arow * DS + ks * 16 + (lane >> 4) * 8) * 2;
            ldsm_x4(p, sb + SP + aoff);
            #pragma unroll
            for (int t = 0; t < 4; t++) {
                uint32_t v[4];
                int vrow = ks * 16 + (lane & 15);
                int vcol = (2 * t + (lane >> 4)) * 8;
                ldsm_x4_t(v, kb + 9216 + (uint32_t)(vrow * DS + vcol) * 2);
                mma_f16(o[2 * t + 0], p, &v[0]);
                mma_f16(o[2 * t + 1], p, &v[2]);
            }
        }
    }

    #pragma unroll
    for (int half = 0; half < 2; half++) {
        int r = w * 16 + (lane >> 2) + half * 8;
        int n = n0 + r;
        #pragma unroll
        for (int ni = 0; ni < 8; ni++) {
            int c = ni * 8 + (lane & 3) * 2;
            __half2 hp = __floats2half2_rn(o[ni][half * 2] * (1.0f / N_),
                                           o[ni][half * 2 + 1] * (1.0f / N_));
            *(__half2*)(g_attnh + ((size_t)(b * N_ + n)) * 512 + h * 64 + c) = hp;
        }
    }
}

// ---------------- launch -------------------------------------------------------
extern "C" void kernel_launch(void* const* d_in, const int* in_sizes, int n_in,
                              void* d_out, int out_size)
{
    const float* x      = (const float*)d_in[0];
    const float* tlmask = (const float*)d_in[1];
    const float* amask  = (const float*)d_in[2];
    const float* uvqk   = (const float*)d_in[3];
    const float* out_w  = (const float*)d_in[4];
    const float* out_b  = (const float*)d_in[5];
    const float* tw     = (const float*)d_in[6];
    const float* pw     = (const float*)d_in[7];
    const int*   tsraw  = (const int*)d_in[8];
    float*       out    = (float*)d_out;

    const int rows = B_ * N_;   // 16384

    __half *wh, *w2h, *ah, *o2h;
    cudaGetSymbolAddress((void**)&wh,  g_Wh);
    cudaGetSymbolAddress((void**)&w2h, g_W2h);
    cudaGetSymbolAddress((void**)&ah,  g_Ah);
    cudaGetSymbolAddress((void**)&o2h, g_O2h);

    cudaFuncSetAttribute(gemm_mma<1>, cudaFuncAttributeMaxDynamicSharedMemorySize, GEMM_SMEM);
    cudaFuncSetAttribute(gemm_mma<2>, cudaFuncAttributeMaxDynamicSharedMemorySize, GEMM_SMEM);
    cudaFuncSetAttribute(attn_tc, cudaFuncAttributeMaxDynamicSharedMemorySize, ATT_SMEM);

    ts_fix_kernel<<<(B_ * NP1 + 255) / 256, 256>>>(tsraw);
    tileflag_kernel<<<64, 256>>>(amask);
    wprep_kernel<<<dim3(G_ / 32, F_ / 32), dim3(32, 8)>>>(uvqk, wh, G_);
    wprep_kernel<<<dim3(512 / 32, F_ / 32), dim3(32, 8)>>>(out_w, w2h, 512);
    ln1_kernel<<<rows, 256>>>(x, tlmask);

    dim3 g1(G_ / 128, rows / 128);
    gemm_mma<1><<<g1, 256, GEMM_SMEM>>>(ah, wh, tlmask, nullptr, nullptr, nullptr);

    relprep_kernel<<<B_ * N_ * N_ / 1024, 256>>>(tw, pw, amask, tlmask);

    dim3 ga(N_ / 128, H_, B_);
    attn_tc<<<ga, 256, ATT_SMEM>>>();

    ln2_kernel<<<rows, 256>>>(tlmask);

    dim3 g2(512 / 128, rows / 128);
    gemm_mma<2><<<g2, 256, GEMM_SMEM>>>(o2h, w2h, nullptr, out_b, x, out);
}